// round 7
// baseline (speedup 1.0000x reference)
#include <cuda_runtime.h>
#include <cstddef>
#include <cstdint>

// Problem constants
// S=128, L=512, IN_DIM=256, PROJ=32, OUT=128
#define S_DIM 128
#define L_DIM 512
#define IN_DIM 256
#define PROJ 32
#define OUT_F 128

using ull = unsigned long long;

__device__ __forceinline__ ull pack2(float lo, float hi) {
    ull r; asm("mov.b64 %0, {%1,%2};" : "=l"(r) : "f"(lo), "f"(hi)); return r;
}
__device__ __forceinline__ void unpack2(ull v, float& lo, float& hi) {
    asm("mov.b64 {%0,%1}, %2;" : "=f"(lo), "=f"(hi) : "l"(v));
}
__device__ __forceinline__ void fma2(ull& d, ull a, ull b) {
    asm("fma.rn.f32x2 %0, %1, %2, %0;" : "+l"(d) : "l"(a), "l"(b));
}

// Scratch: l[s,i,d] stored as Lbuf[(i*128+s)*32+d]; r[s,j,e] as Rbuf[(s*512+j)*32+e]
__device__ float g_Lbuf[L_DIM * S_DIM * PROJ];   // 8 MB
__device__ float g_Rbuf[S_DIM * L_DIM * PROJ];   // 8 MB

// ---------------------------------------------------------------------------
// Kernel A: LayerNorm + projection + mask, scatter into Lbuf / Rbuf.
// act[row,k] = rs*(dot(x_row, Wk) - mu*sumW_k) + b_k, times mask[row].
// Block: 256 threads, 8 rows per block (warp w <-> row w). Grid: 8192.
// smem: W transposed [c][k] pitch 66 + 8 rows of x + sumW.
// ---------------------------------------------------------------------------
#define KA_WPITCH 66
#define KA_SMEM_FLOATS (IN_DIM * KA_WPITCH + 8 * IN_DIM + 64)

__global__ void __launch_bounds__(256) Node2Edge_kA(
    const float* __restrict__ x, const float* __restrict__ mask,
    const float* __restrict__ W, const float* __restrict__ b)
{
    extern __shared__ float sma[];
    float* W_sm  = sma;                              // 256*66
    float* x_sm  = sma + IN_DIM * KA_WPITCH;         // 8*256
    float* sW_sm = x_sm + 8 * IN_DIM;                // 64

    const int t = threadIdx.x;

    // Load W (64x256) transposed into W_sm[c*66 + k]
    {
        const float4* Wg = (const float4*)W;
        #pragma unroll
        for (int q = 0; q < 16; q++) {
            int i4 = t + 256 * q;           // 4096 float4 total
            float4 v = Wg[i4];
            int lin = i4 * 4;
            int k = lin >> 8, c = lin & 255;
            W_sm[(c + 0) * KA_WPITCH + k] = v.x;
            W_sm[(c + 1) * KA_WPITCH + k] = v.y;
            W_sm[(c + 2) * KA_WPITCH + k] = v.z;
            W_sm[(c + 3) * KA_WPITCH + k] = v.w;
        }
    }
    // Load 8 rows of x (2048 floats)
    const int row0 = blockIdx.x * 8;
    {
        const float4* xs = (const float4*)(x + (size_t)row0 * IN_DIM);
        float4* xd = (float4*)x_sm;
        xd[t] = xs[t];
        xd[t + 256] = xs[t + 256];
    }
    __syncthreads();

    // sumW[k] = sum_c W[k][c]
    if (t < 64) {
        float s = 0.f;
        #pragma unroll 8
        for (int c = 0; c < IN_DIM; c++) s += W_sm[c * KA_WPITCH + t];
        sW_sm[t] = s;
    }

    const int w = t >> 5, lane = t & 31;     // warp w handles row w
    // LN stats (raw moments)
    float s1 = 0.f, s2 = 0.f;
    #pragma unroll
    for (int q = 0; q < 8; q++) {
        float v = x_sm[w * IN_DIM + lane + 32 * q];
        s1 += v; s2 += v * v;
    }
    #pragma unroll
    for (int off = 16; off; off >>= 1) {
        s1 += __shfl_xor_sync(0xffffffffu, s1, off);
        s2 += __shfl_xor_sync(0xffffffffu, s2, off);
    }
    const float mu  = s1 * (1.f / 256.f);
    const float var = s2 * (1.f / 256.f) - mu * mu;
    const float rs  = rsqrtf(var + 1e-5f);

    __syncthreads();   // sW_sm ready for everyone

    // Projection: thread computes outputs k0=2*lane, k1=2*lane+1 for row w.
    float a0 = 0.f, a1 = 0.f;
    {
        const float* xr = x_sm + w * IN_DIM;
        const float* wp = W_sm + 2 * lane;
        #pragma unroll 8
        for (int c = 0; c < IN_DIM; c += 4) {
            float4 xv = *(const float4*)&xr[c];
            float2 p0 = *(const float2*)&wp[(c + 0) * KA_WPITCH];
            float2 p1 = *(const float2*)&wp[(c + 1) * KA_WPITCH];
            float2 p2 = *(const float2*)&wp[(c + 2) * KA_WPITCH];
            float2 p3 = *(const float2*)&wp[(c + 3) * KA_WPITCH];
            a0 += xv.x * p0.x; a1 += xv.x * p0.y;
            a0 += xv.y * p1.x; a1 += xv.y * p1.y;
            a0 += xv.z * p2.x; a1 += xv.z * p2.y;
            a0 += xv.w * p3.x; a1 += xv.w * p3.y;
        }
    }
    const int row = row0 + w;
    const float m = mask[row];
    const int k0 = 2 * lane;
    float v0 = (rs * (a0 - mu * sW_sm[k0    ]) + b[k0    ]) * m;
    float v1 = (rs * (a1 - mu * sW_sm[k0 + 1]) + b[k0 + 1]) * m;

    const int s = row >> 9;          // s index (0..127)
    const int ip = row & 511;        // position along L (0..511)
    if (lane < 16) {
        // l part: k0 in [0,32)
        *(float2*)&g_Lbuf[((size_t)ip * S_DIM + s) * PROJ + k0] = make_float2(v0, v1);
    } else {
        // r part: k0-32 in [0,32)
        *(float2*)&g_Rbuf[((size_t)s * L_DIM + ip) * PROJ + (k0 - 32)] = make_float2(v0, v1);
    }
}

// ---------------------------------------------------------------------------
// Kernel B: per (i, j-tile of 32):
//   stage 1: G[d,j,e] = sum_s l[s,i,d] * r[s,j,e]   (regs -> smem)
//   stage 2: out[i,j,f] = (sum_{d,e} G[d,j,e]*W[d,e,f] + bias[f]) / (norm+1e-3)
// 256 threads. All inner math in packed fma.rn.f32x2.
// ---------------------------------------------------------------------------
#define GP 33                       // padded e-dim
#define SC 8                        // s-chunk size
// smem floats: l 4096 | G 32*32*33=33792 | rc 2*8192=16384 | normr 32 | mi 128
#define KB_L_OFF    0
#define KB_G_OFF    4096
#define KB_RC_OFF   (4096 + 32 * 32 * GP)
#define KB_NR_OFF   (KB_RC_OFF + 16384)
#define KB_MI_OFF   (KB_NR_OFF + 32)
#define KB_SMEM_FLOATS (KB_MI_OFF + 128)

__global__ void __launch_bounds__(256, 1) Node2Edge_kB(
    const float* __restrict__ Wout, const float* __restrict__ bias,
    const float* __restrict__ mask, float* __restrict__ out)
{
    extern __shared__ float smb[];
    float* l_sm  = smb + KB_L_OFF;
    float* G_sm  = smb + KB_G_OFF;
    float* rc    = smb + KB_RC_OFF;
    float* normr = smb + KB_NR_OFF;
    float* mi    = smb + KB_MI_OFF;
    float* mj    = G_sm;             // alias: G not yet live

    const int t  = threadIdx.x;
    const int i  = blockIdx.y;
    const int j0 = blockIdx.x * 32;

    // --- async prefetch of r chunk 0 ---
    auto issue_chunk = [&](int ch, int buf) {
        unsigned dst0 = (unsigned)__cvta_generic_to_shared(rc + buf * 8192);
        const float* src0 = g_Rbuf + ((size_t)ch * SC * L_DIM + j0) * PROJ;
        #pragma unroll
        for (int q = 0; q < 8; q++) {
            int v = t + 256 * q;                 // 2048 16B chunks
            int f16 = v & 7;
            int j   = (v >> 3) & 31;
            int s   = v >> 8;
            unsigned dst = dst0 + (unsigned)(((s * 32 + j) * 32 + f16 * 4) * 4);
            const float* src = src0 + ((size_t)s * L_DIM + j) * PROJ + f16 * 4;
            asm volatile("cp.async.cg.shared.global [%0], [%1], 16;" :: "r"(dst), "l"(src));
        }
        asm volatile("cp.async.commit_group;" ::: "memory");
    };
    issue_chunk(0, 0);

    // load l_sm: 4096 floats for row i
    {
        const float4* Ls = (const float4*)(g_Lbuf + (size_t)i * S_DIM * PROJ);
        float4* Ld = (float4*)l_sm;
        #pragma unroll
        for (int q = 0; q < 4; q++) Ld[t + 256 * q] = Ls[t + 256 * q];
    }
    // mask column i and columns j0..j0+31
    if (t < 128) mi[t] = mask[t * L_DIM + i];
    #pragma unroll
    for (int q = 0; q < 16; q++) {
        int v = t + 256 * q;                     // 4096
        int s = v >> 5, j = v & 31;
        mj[v] = mask[s * L_DIM + j0 + j];
    }
    __syncthreads();
    if (t < 32) {
        float acc = 0.f;
        #pragma unroll 8
        for (int s = 0; s < S_DIM; s++) acc += mi[s] * mj[s * 32 + t];
        normr[t] = 1.0f / (acc + 0.001f);
    }
    __syncthreads();                             // mj (G_sm) free after this

    // ================= stage 1 =================
    const int e  = t & 31;
    const int jq = t >> 5;                       // 0..7 ; this thread's j = jq*4+jj
    ull acc[4][16];
    #pragma unroll
    for (int a = 0; a < 4; a++)
        #pragma unroll
        for (int d2 = 0; d2 < 16; d2++) acc[a][d2] = 0ULL;

    #pragma unroll 1
    for (int ch = 0; ch < S_DIM / SC; ch++) {
        if (ch + 1 < S_DIM / SC) {
            issue_chunk(ch + 1, (ch + 1) & 1);
            asm volatile("cp.async.wait_group 1;" ::: "memory");
        } else {
            asm volatile("cp.async.wait_group 0;" ::: "memory");
        }
        __syncthreads();
        const float* rbuf = rc + (ch & 1) * 8192;
        #pragma unroll
        for (int s = 0; s < SC; s++) {
            ull lv[16];
            const ulonglong2* lrow = (const ulonglong2*)(l_sm + (ch * SC + s) * 32);
            #pragma unroll
            for (int q = 0; q < 8; q++) { ulonglong2 u = lrow[q]; lv[2*q] = u.x; lv[2*q+1] = u.y; }
            #pragma unroll
            for (int jj = 0; jj < 4; jj++) {
                float rv = rbuf[(s * 32 + jq * 4 + jj) * 32 + e];
                ull rr = pack2(rv, rv);
                #pragma unroll
                for (int d2 = 0; d2 < 16; d2++) fma2(acc[jj][d2], lv[d2], rr);
            }
        }
        __syncthreads();
    }

    // prefetch W slice for d={0,1} into rc (rc free now as W double-buffer)
    float* wbuf = rc;
    auto issue_w = [&](int dd, int buf) {
        unsigned dst0 = (unsigned)__cvta_generic_to_shared(wbuf + buf * 8192);
        const float* src0 = Wout + (size_t)dd * 8192;
        #pragma unroll
        for (int q = 0; q < 8; q++) {
            int v = t + 256 * q;                 // 2048 float4
            asm volatile("cp.async.cg.shared.global [%0], [%1], 16;"
                         :: "r"(dst0 + (unsigned)(v * 16)), "l"(src0 + v * 4));
        }
        asm volatile("cp.async.commit_group;" ::: "memory");
    };
    issue_w(0, 0);

    // write G: G_sm[(d*32 + j)*33 + e]
    #pragma unroll
    for (int jj = 0; jj < 4; jj++) {
        int j = jq * 4 + jj;
        #pragma unroll
        for (int d2 = 0; d2 < 16; d2++) {
            float g0, g1; unpack2(acc[jj][d2], g0, g1);
            G_sm[((2 * d2    ) * 32 + j) * GP + e] = g0;
            G_sm[((2 * d2 + 1) * 32 + j) * GP + e] = g1;
        }
    }
    __syncthreads();

    // ================= stage 2 =================
    const int j  = t & 31;
    const int fb = t >> 5;                       // f0 = fb*16
    ull acc2[8];
    #pragma unroll
    for (int p = 0; p < 8; p++) acc2[p] = 0ULL;

    #pragma unroll 1
    for (int dd = 0; dd < 16; dd++) {
        if (dd + 1 < 16) {
            issue_w(dd + 1, (dd + 1) & 1);
            asm volatile("cp.async.wait_group 1;" ::: "memory");
        } else {
            asm volatile("cp.async.wait_group 0;" ::: "memory");
        }
        __syncthreads();
        const float* wb = wbuf + (dd & 1) * 8192;
        #pragma unroll
        for (int dl = 0; dl < 2; dl++) {
            const int d = dd * 2 + dl;
            const float* grow = G_sm + (d * 32 + j) * GP;
            const float* wd   = wb + dl * 4096 + fb * 16;
            #pragma unroll
            for (int ee = 0; ee < 32; ee++) {
                float g = grow[ee];
                ull gg = pack2(g, g);
                const ulonglong2* wp = (const ulonglong2*)(wd + ee * 128);
                #pragma unroll
                for (int p2 = 0; p2 < 4; p2++) {
                    ulonglong2 wv = wp[p2];
                    fma2(acc2[2 * p2    ], wv.x, gg);
                    fma2(acc2[2 * p2 + 1], wv.y, gg);
                }
            }
        }
        __syncthreads();
    }

    // epilogue
    const float nr = normr[j];
    const float4* bq = (const float4*)(bias + fb * 16);
    float* op = out + (size_t)i * (L_DIM * OUT_F) + (size_t)(j0 + j) * OUT_F + fb * 16;
    #pragma unroll
    for (int p2 = 0; p2 < 4; p2++) {
        float v0, v1, v2, v3;
        unpack2(acc2[2 * p2    ], v0, v1);
        unpack2(acc2[2 * p2 + 1], v2, v3);
        float4 bb = bq[p2];
        float4 o;
        o.x = (v0 + bb.x) * nr;
        o.y = (v1 + bb.y) * nr;
        o.z = (v2 + bb.z) * nr;
        o.w = (v3 + bb.w) * nr;
        ((float4*)op)[p2] = o;
    }
}

// ---------------------------------------------------------------------------
extern "C" void kernel_launch(void* const* d_in, const int* in_sizes, int n_in,
                              void* d_out, int out_size)
{
    const float* node_repr  = (const float*)d_in[0];
    const float* mask       = (const float*)d_in[1];
    const float* w_proj     = (const float*)d_in[2];
    const float* b_proj     = (const float*)d_in[3];
    const float* out_w      = (const float*)d_in[4];
    const float* out_bias   = (const float*)d_in[5];
    float* out = (float*)d_out;

    const int smemA = KA_SMEM_FLOATS * 4;
    const int smemB = KB_SMEM_FLOATS * 4;
    cudaFuncSetAttribute(Node2Edge_kA, cudaFuncAttributeMaxDynamicSharedMemorySize, smemA);
    cudaFuncSetAttribute(Node2Edge_kB, cudaFuncAttributeMaxDynamicSharedMemorySize, smemB);

    Node2Edge_kA<<<(S_DIM * L_DIM) / 8, 256, smemA>>>(node_repr, mask, w_proj, b_proj);
    Node2Edge_kB<<<dim3(L_DIM / 32, L_DIM), 256, smemB>>>(out_w, out_bias, mask, out);
}

// round 8
// speedup vs baseline: 1.0007x; 1.0007x over previous
#include <cuda_runtime.h>
#include <cstddef>
#include <cstdint>

// Problem constants
// S=128, L=512, IN_DIM=256, PROJ=32, OUT=128
#define S_DIM 128
#define L_DIM 512
#define IN_DIM 256
#define PROJ 32
#define OUT_F 128

using ull = unsigned long long;

__device__ __forceinline__ ull pack2(float lo, float hi) {
    ull r; asm("mov.b64 %0, {%1,%2};" : "=l"(r) : "f"(lo), "f"(hi)); return r;
}
__device__ __forceinline__ void unpack2(ull v, float& lo, float& hi) {
    asm("mov.b64 {%0,%1}, %2;" : "=f"(lo), "=f"(hi) : "l"(v));
}
__device__ __forceinline__ void fma2(ull& d, ull a, ull b) {
    asm("fma.rn.f32x2 %0, %1, %2, %0;" : "+l"(d) : "l"(a), "l"(b));
}

// Scratch: l[s,i,d] stored as Lbuf[(i*128+s)*32+d]; r[s,j,e] as Rbuf[(s*512+j)*32+e]
__device__ float g_Lbuf[L_DIM * S_DIM * PROJ];   // 8 MB
__device__ float g_Rbuf[S_DIM * L_DIM * PROJ];   // 8 MB

// ---------------------------------------------------------------------------
// Kernel A: LayerNorm + projection + mask, scatter into Lbuf / Rbuf.
// act[row,k] = rs*(dot(x_row, Wk) - mu*sumW_k) + b_k, times mask[row].
// Block: 256 threads, 8 rows per block (warp w <-> row w). Grid: 8192.
// smem: W transposed [c][k] pitch 66 + 8 rows of x + sumW.
// ---------------------------------------------------------------------------
#define KA_WPITCH 66
#define KA_SMEM_FLOATS (IN_DIM * KA_WPITCH + 8 * IN_DIM + 64)

__global__ void __launch_bounds__(256) Node2Edge_kA(
    const float* __restrict__ x, const float* __restrict__ mask,
    const float* __restrict__ W, const float* __restrict__ b)
{
    extern __shared__ float sma[];
    float* W_sm  = sma;                              // 256*66
    float* x_sm  = sma + IN_DIM * KA_WPITCH;         // 8*256
    float* sW_sm = x_sm + 8 * IN_DIM;                // 64

    const int t = threadIdx.x;

    // Load W (64x256) transposed into W_sm[c*66 + k]
    {
        const float4* Wg = (const float4*)W;
        #pragma unroll
        for (int q = 0; q < 16; q++) {
            int i4 = t + 256 * q;           // 4096 float4 total
            float4 v = Wg[i4];
            int lin = i4 * 4;
            int k = lin >> 8, c = lin & 255;
            W_sm[(c + 0) * KA_WPITCH + k] = v.x;
            W_sm[(c + 1) * KA_WPITCH + k] = v.y;
            W_sm[(c + 2) * KA_WPITCH + k] = v.z;
            W_sm[(c + 3) * KA_WPITCH + k] = v.w;
        }
    }
    // Load 8 rows of x (2048 floats)
    const int row0 = blockIdx.x * 8;
    {
        const float4* xs = (const float4*)(x + (size_t)row0 * IN_DIM);
        float4* xd = (float4*)x_sm;
        xd[t] = xs[t];
        xd[t + 256] = xs[t + 256];
    }
    __syncthreads();

    // sumW[k] = sum_c W[k][c]
    if (t < 64) {
        float s = 0.f;
        #pragma unroll 8
        for (int c = 0; c < IN_DIM; c++) s += W_sm[c * KA_WPITCH + t];
        sW_sm[t] = s;
    }

    const int w = t >> 5, lane = t & 31;     // warp w handles row w
    // LN stats (raw moments)
    float s1 = 0.f, s2 = 0.f;
    #pragma unroll
    for (int q = 0; q < 8; q++) {
        float v = x_sm[w * IN_DIM + lane + 32 * q];
        s1 += v; s2 += v * v;
    }
    #pragma unroll
    for (int off = 16; off; off >>= 1) {
        s1 += __shfl_xor_sync(0xffffffffu, s1, off);
        s2 += __shfl_xor_sync(0xffffffffu, s2, off);
    }
    const float mu  = s1 * (1.f / 256.f);
    const float var = s2 * (1.f / 256.f) - mu * mu;
    const float rs  = rsqrtf(var + 1e-5f);

    __syncthreads();   // sW_sm ready for everyone

    // Projection: thread computes outputs k0=2*lane, k1=2*lane+1 for row w.
    float a0 = 0.f, a1 = 0.f;
    {
        const float* xr = x_sm + w * IN_DIM;
        const float* wp = W_sm + 2 * lane;
        #pragma unroll 8
        for (int c = 0; c < IN_DIM; c += 4) {
            float4 xv = *(const float4*)&xr[c];
            float2 p0 = *(const float2*)&wp[(c + 0) * KA_WPITCH];
            float2 p1 = *(const float2*)&wp[(c + 1) * KA_WPITCH];
            float2 p2 = *(const float2*)&wp[(c + 2) * KA_WPITCH];
            float2 p3 = *(const float2*)&wp[(c + 3) * KA_WPITCH];
            a0 += xv.x * p0.x; a1 += xv.x * p0.y;
            a0 += xv.y * p1.x; a1 += xv.y * p1.y;
            a0 += xv.z * p2.x; a1 += xv.z * p2.y;
            a0 += xv.w * p3.x; a1 += xv.w * p3.y;
        }
    }
    const int row = row0 + w;
    const float m = mask[row];
    const int k0 = 2 * lane;
    float v0 = (rs * (a0 - mu * sW_sm[k0    ]) + b[k0    ]) * m;
    float v1 = (rs * (a1 - mu * sW_sm[k0 + 1]) + b[k0 + 1]) * m;

    const int s = row >> 9;          // s index (0..127)
    const int ip = row & 511;        // position along L (0..511)
    if (lane < 16) {
        // l part: k0 in [0,32)
        *(float2*)&g_Lbuf[((size_t)ip * S_DIM + s) * PROJ + k0] = make_float2(v0, v1);
    } else {
        // r part: k0-32 in [0,32)
        *(float2*)&g_Rbuf[((size_t)s * L_DIM + ip) * PROJ + (k0 - 32)] = make_float2(v0, v1);
    }
}

// ---------------------------------------------------------------------------
// Kernel B: per (i, j-tile of 32):
//   stage 1: G[d,j,e] = sum_s l[s,i,d] * r[s,j,e]   (regs -> smem)
//   stage 2: out[i,j,f] = (sum_{d,e} G[d,j,e]*W[d,e,f] + bias[f]) / (norm+1e-3)
// 256 threads. All inner math in packed fma.rn.f32x2.
// ---------------------------------------------------------------------------
#define GP 33                       // padded e-dim
#define SC 8                        // s-chunk size
// smem floats: l 4096 | G 32*32*33=33792 | rc 2*8192=16384 | normr 32 | mi 128
#define KB_L_OFF    0
#define KB_G_OFF    4096
#define KB_RC_OFF   (4096 + 32 * 32 * GP)
#define KB_NR_OFF   (KB_RC_OFF + 16384)
#define KB_MI_OFF   (KB_NR_OFF + 32)
#define KB_SMEM_FLOATS (KB_MI_OFF + 128)

__global__ void __launch_bounds__(256, 1) Node2Edge_kB(
    const float* __restrict__ Wout, const float* __restrict__ bias,
    const float* __restrict__ mask, float* __restrict__ out)
{
    extern __shared__ float smb[];
    float* l_sm  = smb + KB_L_OFF;
    float* G_sm  = smb + KB_G_OFF;
    float* rc    = smb + KB_RC_OFF;
    float* normr = smb + KB_NR_OFF;
    float* mi    = smb + KB_MI_OFF;
    float* mj    = G_sm;             // alias: G not yet live

    const int t  = threadIdx.x;
    const int i  = blockIdx.y;
    const int j0 = blockIdx.x * 32;

    // --- async prefetch of r chunk 0 ---
    auto issue_chunk = [&](int ch, int buf) {
        unsigned dst0 = (unsigned)__cvta_generic_to_shared(rc + buf * 8192);
        const float* src0 = g_Rbuf + ((size_t)ch * SC * L_DIM + j0) * PROJ;
        #pragma unroll
        for (int q = 0; q < 8; q++) {
            int v = t + 256 * q;                 // 2048 16B chunks
            int f16 = v & 7;
            int j   = (v >> 3) & 31;
            int s   = v >> 8;
            unsigned dst = dst0 + (unsigned)(((s * 32 + j) * 32 + f16 * 4) * 4);
            const float* src = src0 + ((size_t)s * L_DIM + j) * PROJ + f16 * 4;
            asm volatile("cp.async.cg.shared.global [%0], [%1], 16;" :: "r"(dst), "l"(src));
        }
        asm volatile("cp.async.commit_group;" ::: "memory");
    };
    issue_chunk(0, 0);

    // load l_sm: 4096 floats for row i
    {
        const float4* Ls = (const float4*)(g_Lbuf + (size_t)i * S_DIM * PROJ);
        float4* Ld = (float4*)l_sm;
        #pragma unroll
        for (int q = 0; q < 4; q++) Ld[t + 256 * q] = Ls[t + 256 * q];
    }
    // mask column i and columns j0..j0+31
    if (t < 128) mi[t] = mask[t * L_DIM + i];
    #pragma unroll
    for (int q = 0; q < 16; q++) {
        int v = t + 256 * q;                     // 4096
        int s = v >> 5, j = v & 31;
        mj[v] = mask[s * L_DIM + j0 + j];
    }
    __syncthreads();
    if (t < 32) {
        float acc = 0.f;
        #pragma unroll 8
        for (int s = 0; s < S_DIM; s++) acc += mi[s] * mj[s * 32 + t];
        normr[t] = 1.0f / (acc + 0.001f);
    }
    __syncthreads();                             // mj (G_sm) free after this

    // ================= stage 1 =================
    const int e  = t & 31;
    const int jq = t >> 5;                       // 0..7 ; this thread's j = jq*4+jj
    ull acc[4][16];
    #pragma unroll
    for (int a = 0; a < 4; a++)
        #pragma unroll
        for (int d2 = 0; d2 < 16; d2++) acc[a][d2] = 0ULL;

    #pragma unroll 1
    for (int ch = 0; ch < S_DIM / SC; ch++) {
        if (ch + 1 < S_DIM / SC) {
            issue_chunk(ch + 1, (ch + 1) & 1);
            asm volatile("cp.async.wait_group 1;" ::: "memory");
        } else {
            asm volatile("cp.async.wait_group 0;" ::: "memory");
        }
        __syncthreads();
        const float* rbuf = rc + (ch & 1) * 8192;
        #pragma unroll
        for (int s = 0; s < SC; s++) {
            ull lv[16];
            const ulonglong2* lrow = (const ulonglong2*)(l_sm + (ch * SC + s) * 32);
            #pragma unroll
            for (int q = 0; q < 8; q++) { ulonglong2 u = lrow[q]; lv[2*q] = u.x; lv[2*q+1] = u.y; }
            #pragma unroll
            for (int jj = 0; jj < 4; jj++) {
                float rv = rbuf[(s * 32 + jq * 4 + jj) * 32 + e];
                ull rr = pack2(rv, rv);
                #pragma unroll
                for (int d2 = 0; d2 < 16; d2++) fma2(acc[jj][d2], lv[d2], rr);
            }
        }
        __syncthreads();
    }

    // prefetch W slice for d={0,1} into rc (rc free now as W double-buffer)
    float* wbuf = rc;
    auto issue_w = [&](int dd, int buf) {
        unsigned dst0 = (unsigned)__cvta_generic_to_shared(wbuf + buf * 8192);
        const float* src0 = Wout + (size_t)dd * 8192;
        #pragma unroll
        for (int q = 0; q < 8; q++) {
            int v = t + 256 * q;                 // 2048 float4
            asm volatile("cp.async.cg.shared.global [%0], [%1], 16;"
                         :: "r"(dst0 + (unsigned)(v * 16)), "l"(src0 + v * 4));
        }
        asm volatile("cp.async.commit_group;" ::: "memory");
    };
    issue_w(0, 0);

    // write G: G_sm[(d*32 + j)*33 + e]
    #pragma unroll
    for (int jj = 0; jj < 4; jj++) {
        int j = jq * 4 + jj;
        #pragma unroll
        for (int d2 = 0; d2 < 16; d2++) {
            float g0, g1; unpack2(acc[jj][d2], g0, g1);
            G_sm[((2 * d2    ) * 32 + j) * GP + e] = g0;
            G_sm[((2 * d2 + 1) * 32 + j) * GP + e] = g1;
        }
    }
    __syncthreads();

    // ================= stage 2 =================
    const int j  = t & 31;
    const int fb = t >> 5;                       // f0 = fb*16
    ull acc2[8];
    #pragma unroll
    for (int p = 0; p < 8; p++) acc2[p] = 0ULL;

    #pragma unroll 1
    for (int dd = 0; dd < 16; dd++) {
        if (dd + 1 < 16) {
            issue_w(dd + 1, (dd + 1) & 1);
            asm volatile("cp.async.wait_group 1;" ::: "memory");
        } else {
            asm volatile("cp.async.wait_group 0;" ::: "memory");
        }
        __syncthreads();
        const float* wb = wbuf + (dd & 1) * 8192;
        #pragma unroll
        for (int dl = 0; dl < 2; dl++) {
            const int d = dd * 2 + dl;
            const float* grow = G_sm + (d * 32 + j) * GP;
            const float* wd   = wb + dl * 4096 + fb * 16;
            #pragma unroll
            for (int ee = 0; ee < 32; ee++) {
                float g = grow[ee];
                ull gg = pack2(g, g);
                const ulonglong2* wp = (const ulonglong2*)(wd + ee * 128);
                #pragma unroll
                for (int p2 = 0; p2 < 4; p2++) {
                    ulonglong2 wv = wp[p2];
                    fma2(acc2[2 * p2    ], wv.x, gg);
                    fma2(acc2[2 * p2 + 1], wv.y, gg);
                }
            }
        }
        __syncthreads();
    }

    // epilogue
    const float nr = normr[j];
    const float4* bq = (const float4*)(bias + fb * 16);
    float* op = out + (size_t)i * (L_DIM * OUT_F) + (size_t)(j0 + j) * OUT_F + fb * 16;
    #pragma unroll
    for (int p2 = 0; p2 < 4; p2++) {
        float v0, v1, v2, v3;
        unpack2(acc2[2 * p2    ], v0, v1);
        unpack2(acc2[2 * p2 + 1], v2, v3);
        float4 bb = bq[p2];
        float4 o;
        o.x = (v0 + bb.x) * nr;
        o.y = (v1 + bb.y) * nr;
        o.z = (v2 + bb.z) * nr;
        o.w = (v3 + bb.w) * nr;
        ((float4*)op)[p2] = o;
    }
}

// ---------------------------------------------------------------------------
extern "C" void kernel_launch(void* const* d_in, const int* in_sizes, int n_in,
                              void* d_out, int out_size)
{
    const float* node_repr  = (const float*)d_in[0];
    const float* mask       = (const float*)d_in[1];
    const float* w_proj     = (const float*)d_in[2];
    const float* b_proj     = (const float*)d_in[3];
    const float* out_w      = (const float*)d_in[4];
    const float* out_bias   = (const float*)d_in[5];
    float* out = (float*)d_out;

    const int smemA = KA_SMEM_FLOATS * 4;
    const int smemB = KB_SMEM_FLOATS * 4;
    cudaFuncSetAttribute(Node2Edge_kA, cudaFuncAttributeMaxDynamicSharedMemorySize, smemA);
    cudaFuncSetAttribute(Node2Edge_kB, cudaFuncAttributeMaxDynamicSharedMemorySize, smemB);

    Node2Edge_kA<<<(S_DIM * L_DIM) / 8, 256, smemA>>>(node_repr, mask, w_proj, b_proj);
    Node2Edge_kB<<<dim3(L_DIM / 32, L_DIM), 256, smemB>>>(out_w, out_bias, mask, out);
}

// round 10
// speedup vs baseline: 1.1634x; 1.1626x over previous
#include <cuda_runtime.h>
#include <cstddef>
#include <cstdint>

#define S_DIM 128
#define L_DIM 512
#define IN_DIM 256
#define PROJ 32
#define OUT_F 128
#define JT 16

using ull = unsigned long long;

__device__ __forceinline__ ull pack2(float lo, float hi) {
    ull r; asm("mov.b64 %0, {%1,%2};" : "=l"(r) : "f"(lo), "f"(hi)); return r;
}
__device__ __forceinline__ void unpack2(ull v, float& lo, float& hi) {
    asm("mov.b64 {%0,%1}, %2;" : "=f"(lo), "=f"(hi) : "l"(v));
}
__device__ __forceinline__ void fma2(ull& d, ull a, ull b) {
    asm("fma.rn.f32x2 %0, %1, %2, %0;" : "+l"(d) : "l"(a), "l"(b));
}
__device__ __forceinline__ void cp16(unsigned dst, const void* src) {
    asm volatile("cp.async.cg.shared.global [%0], [%1], 16;" :: "r"(dst), "l"(src));
}
__device__ __forceinline__ void cpcommit() { asm volatile("cp.async.commit_group;" ::: "memory"); }
__device__ __forceinline__ void cpwait1()  { asm volatile("cp.async.wait_group 1;" ::: "memory"); }
__device__ __forceinline__ void cpwait0()  { asm volatile("cp.async.wait_group 0;" ::: "memory"); }

// l[s,i,d] as Lbuf[(i*128+s)*32+d]; r[s,j,e] as Rbuf[(s*512+j)*32+e]
__device__ float g_Lbuf[L_DIM * S_DIM * PROJ];   // 8 MB
__device__ float g_Rbuf[S_DIM * L_DIM * PROJ];   // 8 MB

// ---------------------------------------------------------------------------
// Kernel A: LayerNorm + projection + mask. 8 rows/block (proven).
// ---------------------------------------------------------------------------
#define KA_WPITCH 66
#define KA_SMEM_FLOATS (IN_DIM * KA_WPITCH + 8 * IN_DIM + 64)

__global__ void __launch_bounds__(256) Node2Edge_kA(
    const float* __restrict__ x, const float* __restrict__ mask,
    const float* __restrict__ W, const float* __restrict__ b)
{
    extern __shared__ float sma[];
    float* W_sm  = sma;
    float* x_sm  = sma + IN_DIM * KA_WPITCH;
    float* sW_sm = x_sm + 8 * IN_DIM;
    const int t = threadIdx.x;

    {
        const float4* Wg = (const float4*)W;
        #pragma unroll
        for (int q = 0; q < 16; q++) {
            int i4 = t + 256 * q;
            float4 v = Wg[i4];
            int lin = i4 * 4;
            int k = lin >> 8, c = lin & 255;
            W_sm[(c + 0) * KA_WPITCH + k] = v.x;
            W_sm[(c + 1) * KA_WPITCH + k] = v.y;
            W_sm[(c + 2) * KA_WPITCH + k] = v.z;
            W_sm[(c + 3) * KA_WPITCH + k] = v.w;
        }
    }
    const int row0 = blockIdx.x * 8;
    {
        const float4* xs = (const float4*)(x + (size_t)row0 * IN_DIM);
        float4* xd = (float4*)x_sm;
        xd[t] = xs[t];
        xd[t + 256] = xs[t + 256];
    }
    __syncthreads();

    if (t < 64) {
        float s = 0.f;
        #pragma unroll 8
        for (int c = 0; c < IN_DIM; c++) s += W_sm[c * KA_WPITCH + t];
        sW_sm[t] = s;
    }

    const int w = t >> 5, lane = t & 31;
    float s1 = 0.f, s2 = 0.f;
    #pragma unroll
    for (int q = 0; q < 8; q++) {
        float v = x_sm[w * IN_DIM + lane + 32 * q];
        s1 += v; s2 += v * v;
    }
    #pragma unroll
    for (int off = 16; off; off >>= 1) {
        s1 += __shfl_xor_sync(0xffffffffu, s1, off);
        s2 += __shfl_xor_sync(0xffffffffu, s2, off);
    }
    const float mu  = s1 * (1.f / 256.f);
    const float var = s2 * (1.f / 256.f) - mu * mu;
    const float rs  = rsqrtf(var + 1e-5f);
    __syncthreads();

    float a0 = 0.f, a1 = 0.f;
    {
        const float* xr = x_sm + w * IN_DIM;
        const float* wp = W_sm + 2 * lane;
        #pragma unroll 8
        for (int c = 0; c < IN_DIM; c += 4) {
            float4 xv = *(const float4*)&xr[c];
            float2 p0 = *(const float2*)&wp[(c + 0) * KA_WPITCH];
            float2 p1 = *(const float2*)&wp[(c + 1) * KA_WPITCH];
            float2 p2 = *(const float2*)&wp[(c + 2) * KA_WPITCH];
            float2 p3 = *(const float2*)&wp[(c + 3) * KA_WPITCH];
            a0 += xv.x * p0.x; a1 += xv.x * p0.y;
            a0 += xv.y * p1.x; a1 += xv.y * p1.y;
            a0 += xv.z * p2.x; a1 += xv.z * p2.y;
            a0 += xv.w * p3.x; a1 += xv.w * p3.y;
        }
    }
    const int row = row0 + w;
    const float m = mask[row];
    const int k0 = 2 * lane;
    float v0 = (rs * (a0 - mu * sW_sm[k0    ]) + b[k0    ]) * m;
    float v1 = (rs * (a1 - mu * sW_sm[k0 + 1]) + b[k0 + 1]) * m;
    const int s = row >> 9, ip = row & 511;
    if (lane < 16) {
        *(float2*)&g_Lbuf[((size_t)ip * S_DIM + s) * PROJ + k0] = make_float2(v0, v1);
    } else {
        *(float2*)&g_Rbuf[((size_t)s * L_DIM + ip) * PROJ + (k0 - 32)] = make_float2(v0, v1);
    }
}

// ---------------------------------------------------------------------------
// Kernel B (occ 2): per (i, 16-wide j-tile)
//  stage 1: G[j][d][e] = sum_s l[s,i,d]*r[s,j,e]
//  stage 2: out[j,f] = sum_de G * W, W streamed per-d, warps split e 4-way,
//           thread owns 8j x 4f; cross-e reduce via smem.
// smem floats:
//   [0,4096)      l_sm            (stage2: W buf 0; epilogue: partials)
//   [4096,8192)   rc 2x2048 SC=4  (stage2: W buf 1; epilogue: partials)
//   [8192,24576)  G [j][d][e]     (pre-stage1: mjs alias)
//   [24576,24592) normr
//   [24592,24720) mi
// ---------------------------------------------------------------------------
#define KB_G_OFF   8192
#define KB_NR_OFF  24576
#define KB_MI_OFF  24592
#define KB_SMEM_FLOATS 24720

__global__ void __launch_bounds__(256, 2) Node2Edge_kB(
    const float* __restrict__ Wout, const float* __restrict__ bias,
    const float* __restrict__ mask, float* __restrict__ out)
{
    extern __shared__ float smb[];
    float* l_sm  = smb;
    float* rc    = smb + 4096;
    float* G_sm  = smb + KB_G_OFF;
    float* normr = smb + KB_NR_OFF;
    float* mi    = smb + KB_MI_OFF;
    float* mjs   = G_sm;            // alias before stage 1 writes G

    const int t  = threadIdx.x;
    const int i  = blockIdx.y;
    const int j0 = blockIdx.x * JT;

    // r chunk loader: chunk ch = 4 s rows; rbuf[s][j][e]
    auto issue_r = [&](int ch, int buf) {
        unsigned dst0 = (unsigned)__cvta_generic_to_shared(rc + buf * 2048);
        #pragma unroll
        for (int q = 0; q < 2; q++) {
            int v = t + 256 * q;             // 512 float4
            int e4 = v & 7, j = (v >> 3) & 15, s = v >> 7;
            unsigned dst = dst0 + (unsigned)(((s * JT + j) * 32 + e4 * 4) * 4);
            const float* src = g_Rbuf + ((size_t)(ch * 4 + s) * L_DIM + j0 + j) * PROJ + e4 * 4;
            cp16(dst, src);
        }
        cpcommit();
    };
    issue_r(0, 0);

    // l for row i
    {
        const float4* Ls = (const float4*)(g_Lbuf + (size_t)i * S_DIM * PROJ);
        float4* Ld = (float4*)l_sm;
        #pragma unroll
        for (int q = 0; q < 4; q++) Ld[t + 256 * q] = Ls[t + 256 * q];
    }
    // masks
    if (t < 128) mi[t] = mask[t * L_DIM + i];
    #pragma unroll
    for (int q = 0; q < 8; q++) {
        int v = t + 256 * q;                 // 2048 = 128 s x 16 j
        int s = v >> 4, jm = v & 15;
        mjs[v] = mask[s * L_DIM + j0 + jm];
    }
    __syncthreads();
    if (t < JT) {
        float acc = 0.f;
        #pragma unroll 8
        for (int s = 0; s < S_DIM; s++) acc += mi[s] * mjs[s * JT + t];
        normr[t] = 1.0f / (acc + 0.001f);
    }
    __syncthreads();

    // ===== stage 1 =====
    const int e  = t & 31;
    const int jq = t >> 5;                   // warp -> j pair {2jq, 2jq+1}
    ull acc[2][16];
    #pragma unroll
    for (int a = 0; a < 2; a++)
        #pragma unroll
        for (int d2 = 0; d2 < 16; d2++) acc[a][d2] = 0ULL;

    #pragma unroll 1
    for (int ch = 0; ch < 32; ch++) {
        if (ch + 1 < 32) { issue_r(ch + 1, (ch + 1) & 1); cpwait1(); }
        else             { cpwait0(); }
        __syncthreads();
        const float* rbuf = rc + (ch & 1) * 2048;
        #pragma unroll
        for (int s = 0; s < 4; s++) {
            ull lv[16];
            const ulonglong2* lrow = (const ulonglong2*)(l_sm + (ch * 4 + s) * 32);
            #pragma unroll
            for (int q = 0; q < 8; q++) { ulonglong2 u = lrow[q]; lv[2*q] = u.x; lv[2*q+1] = u.y; }
            #pragma unroll
            for (int jj = 0; jj < 2; jj++) {
                float rv = rbuf[(s * JT + jq * 2 + jj) * 32 + e];
                ull rr = pack2(rv, rv);
                #pragma unroll
                for (int d2 = 0; d2 < 16; d2++) fma2(acc[jj][d2], lv[d2], rr);
            }
        }
        __syncthreads();
    }

    // W streamer: per d, 4096 floats into wbuf half [buf*4096, ...)
    auto issue_w = [&](int d, int buf) {
        unsigned dst0 = (unsigned)__cvta_generic_to_shared(smb + buf * 4096);
        const float* src0 = Wout + (size_t)d * 4096;
        #pragma unroll
        for (int q = 0; q < 4; q++) {
            int v = t + 256 * q;             // 1024 float4
            cp16(dst0 + (unsigned)(v * 16), src0 + v * 4);
        }
        cpcommit();
    };
    issue_w(0, 0);   // l_sm/rc region reusable now (all reads done)

    // write G[j][d][e]
    #pragma unroll
    for (int jj = 0; jj < 2; jj++) {
        const int j = jq * 2 + jj;
        #pragma unroll
        for (int d2 = 0; d2 < 16; d2++) {
            float g0, g1; unpack2(acc[jj][d2], g0, g1);
            G_sm[(j * 32 + 2 * d2    ) * 32 + e] = g0;
            G_sm[(j * 32 + 2 * d2 + 1) * 32 + e] = g1;
        }
    }
    __syncthreads();

    // ===== stage 2 =====
    const int fq = t & 31;                   // f = 4*fq
    const int w  = t >> 5;
    const int eh = w & 3;                    // e block [eh*8, eh*8+8)
    const int jh = w >> 2;                   // j block [jh*8, jh*8+8)
    ull a2[8][2];
    #pragma unroll
    for (int j8 = 0; j8 < 8; j8++) { a2[j8][0] = 0ULL; a2[j8][1] = 0ULL; }

    #pragma unroll 1
    for (int d = 0; d < 32; d++) {
        if (d + 1 < 32) { issue_w(d + 1, (d + 1) & 1); cpwait1(); }
        else            { cpwait0(); }
        __syncthreads();
        const float* wb = smb + (d & 1) * 4096;
        #pragma unroll
        for (int eq = 0; eq < 2; eq++) {
            const int e0 = eh * 8 + eq * 4;
            float4 gv[8];
            #pragma unroll
            for (int j8 = 0; j8 < 8; j8++)
                gv[j8] = *(const float4*)&G_sm[((jh * 8 + j8) * 32 + d) * 32 + e0];
            #pragma unroll
            for (int ee = 0; ee < 4; ee++) {
                float4 wv = *(const float4*)&wb[(e0 + ee) * OUT_F + 4 * fq];
                ull w01 = pack2(wv.x, wv.y);
                ull w23 = pack2(wv.z, wv.w);
                #pragma unroll
                for (int j8 = 0; j8 < 8; j8++) {
                    float g = (ee == 0) ? gv[j8].x : (ee == 1) ? gv[j8].y
                            : (ee == 2) ? gv[j8].z : gv[j8].w;
                    ull gg = pack2(g, g);
                    fma2(a2[j8][0], w01, gg);
                    fma2(a2[j8][1], w23, gg);
                }
            }
        }
        __syncthreads();
    }

    // partials -> smem [0, 8192): pbuf[(eh*16 + j)*128 + 4*fq]
    float* pbuf = smb;
    #pragma unroll
    for (int j8 = 0; j8 < 8; j8++) {
        float v0, v1, v2, v3;
        unpack2(a2[j8][0], v0, v1);
        unpack2(a2[j8][1], v2, v3);
        *(float4*)&pbuf[((eh * JT + jh * 8 + j8) * OUT_F) + 4 * fq] = make_float4(v0, v1, v2, v3);
    }
    __syncthreads();

    // reduce over 4 eh groups + epilogue. Tile = 16j x 128f = 512 float4,
    // 256 threads -> 2 each. (R8 bug: this loop ran q<4 and wrote 2x the
    // tile, running past d_out on the last tiles.)
    #pragma unroll
    for (int q = 0; q < 2; q++) {
        int idx4 = t + 256 * q;              // float4 index into [16j x 128f]
        int j = idx4 >> 5;
        const float4* p = (const float4*)pbuf;
        float4 s0 = p[idx4];
        float4 s1 = p[idx4 + 512];
        float4 s2 = p[idx4 + 1024];
        float4 s3 = p[idx4 + 1536];
        float4 bb = ((const float4*)bias)[idx4 & 31];
        float nr = normr[j];
        float4 o;
        o.x = (s0.x + s1.x + s2.x + s3.x + bb.x) * nr;
        o.y = (s0.y + s1.y + s2.y + s3.y + bb.y) * nr;
        o.z = (s0.z + s1.z + s2.z + s3.z + bb.z) * nr;
        o.w = (s0.w + s1.w + s2.w + s3.w + bb.w) * nr;
        ((float4*)(out + (size_t)i * (L_DIM * OUT_F) + (size_t)j0 * OUT_F))[idx4] = o;
    }
}

// ---------------------------------------------------------------------------
extern "C" void kernel_launch(void* const* d_in, const int* in_sizes, int n_in,
                              void* d_out, int out_size)
{
    const float* node_repr = (const float*)d_in[0];
    const float* mask      = (const float*)d_in[1];
    const float* w_proj    = (const float*)d_in[2];
    const float* b_proj    = (const float*)d_in[3];
    const float* out_w     = (const float*)d_in[4];
    const float* out_bias  = (const float*)d_in[5];
    float* out = (float*)d_out;

    const int smemA = KA_SMEM_FLOATS * 4;
    const int smemB = KB_SMEM_FLOATS * 4;
    cudaFuncSetAttribute(Node2Edge_kA, cudaFuncAttributeMaxDynamicSharedMemorySize, smemA);
    cudaFuncSetAttribute(Node2Edge_kB, cudaFuncAttributeMaxDynamicSharedMemorySize, smemB);

    Node2Edge_kA<<<(S_DIM * L_DIM) / 8, 256, smemA>>>(node_repr, mask, w_proj, b_proj);
    Node2Edge_kB<<<dim3(L_DIM / JT, L_DIM), 256, smemB>>>(out_w, out_bias, mask, out);
}

// round 11
// speedup vs baseline: 1.1746x; 1.0096x over previous
#include <cuda_runtime.h>
#include <cstddef>
#include <cstdint>

#define S_DIM 128
#define L_DIM 512
#define IN_DIM 256
#define PROJ 32
#define OUT_F 128
#define JT 16

using ull = unsigned long long;

__device__ __forceinline__ ull pack2(float lo, float hi) {
    ull r; asm("mov.b64 %0, {%1,%2};" : "=l"(r) : "f"(lo), "f"(hi)); return r;
}
__device__ __forceinline__ void unpack2(ull v, float& lo, float& hi) {
    asm("mov.b64 {%0,%1}, %2;" : "=f"(lo), "=f"(hi) : "l"(v));
}
__device__ __forceinline__ void fma2(ull& d, ull a, ull b) {
    asm("fma.rn.f32x2 %0, %1, %2, %0;" : "+l"(d) : "l"(a), "l"(b));
}
__device__ __forceinline__ void cp16(unsigned dst, const void* src) {
    asm volatile("cp.async.cg.shared.global [%0], [%1], 16;" :: "r"(dst), "l"(src));
}
__device__ __forceinline__ void cpcommit() { asm volatile("cp.async.commit_group;" ::: "memory"); }
__device__ __forceinline__ void cpwait2()  { asm volatile("cp.async.wait_group 2;" ::: "memory"); }
__device__ __forceinline__ void cpwait1()  { asm volatile("cp.async.wait_group 1;" ::: "memory"); }
__device__ __forceinline__ void cpwait0()  { asm volatile("cp.async.wait_group 0;" ::: "memory"); }

// l[s,i,d] as Lbuf[(i*128+s)*32+d]; r[s,j,e] as Rbuf[(s*512+j)*32+e]
__device__ float g_Lbuf[L_DIM * S_DIM * PROJ];   // 8 MB
__device__ float g_Rbuf[S_DIM * L_DIM * PROJ];   // 8 MB

// ---------------------------------------------------------------------------
// Kernel A: LayerNorm + projection + mask. 32 rows/block (W amortized 4x).
// ---------------------------------------------------------------------------
#define KA_WPITCH 66
#define KA_SMEM_FLOATS (IN_DIM * KA_WPITCH + 32 * IN_DIM + 64)

__global__ void __launch_bounds__(256) Node2Edge_kA(
    const float* __restrict__ x, const float* __restrict__ mask,
    const float* __restrict__ W, const float* __restrict__ b)
{
    extern __shared__ float sma[];
    float* W_sm  = sma;                              // 256*66
    float* x_sm  = sma + IN_DIM * KA_WPITCH;         // 32*256
    float* sW_sm = x_sm + 32 * IN_DIM;               // 64
    const int t = threadIdx.x;

    {
        const float4* Wg = (const float4*)W;
        #pragma unroll
        for (int q = 0; q < 16; q++) {
            int i4 = t + 256 * q;
            float4 v = Wg[i4];
            int lin = i4 * 4;
            int k = lin >> 8, c = lin & 255;
            W_sm[(c + 0) * KA_WPITCH + k] = v.x;
            W_sm[(c + 1) * KA_WPITCH + k] = v.y;
            W_sm[(c + 2) * KA_WPITCH + k] = v.z;
            W_sm[(c + 3) * KA_WPITCH + k] = v.w;
        }
    }
    const int row0 = blockIdx.x * 32;
    {
        const float4* xs = (const float4*)(x + (size_t)row0 * IN_DIM);
        float4* xd = (float4*)x_sm;
        #pragma unroll
        for (int q = 0; q < 8; q++) xd[t + 256 * q] = xs[t + 256 * q];
    }
    __syncthreads();

    if (t < 64) {
        float s = 0.f;
        #pragma unroll 8
        for (int c = 0; c < IN_DIM; c++) s += W_sm[c * KA_WPITCH + t];
        sW_sm[t] = s;
    }
    __syncthreads();

    const int w = t >> 5, lane = t & 31;
    #pragma unroll 1
    for (int rr = 0; rr < 4; rr++) {
        const int row_local = w * 4 + rr;
        float s1 = 0.f, s2 = 0.f;
        #pragma unroll
        for (int q = 0; q < 8; q++) {
            float v = x_sm[row_local * IN_DIM + lane + 32 * q];
            s1 += v; s2 += v * v;
        }
        #pragma unroll
        for (int off = 16; off; off >>= 1) {
            s1 += __shfl_xor_sync(0xffffffffu, s1, off);
            s2 += __shfl_xor_sync(0xffffffffu, s2, off);
        }
        const float mu  = s1 * (1.f / 256.f);
        const float var = s2 * (1.f / 256.f) - mu * mu;
        const float rs  = rsqrtf(var + 1e-5f);

        float a0 = 0.f, a1 = 0.f;
        {
            const float* xr = x_sm + row_local * IN_DIM;
            const float* wp = W_sm + 2 * lane;
            #pragma unroll 8
            for (int c = 0; c < IN_DIM; c += 4) {
                float4 xv = *(const float4*)&xr[c];
                float2 p0 = *(const float2*)&wp[(c + 0) * KA_WPITCH];
                float2 p1 = *(const float2*)&wp[(c + 1) * KA_WPITCH];
                float2 p2 = *(const float2*)&wp[(c + 2) * KA_WPITCH];
                float2 p3 = *(const float2*)&wp[(c + 3) * KA_WPITCH];
                a0 += xv.x * p0.x; a1 += xv.x * p0.y;
                a0 += xv.y * p1.x; a1 += xv.y * p1.y;
                a0 += xv.z * p2.x; a1 += xv.z * p2.y;
                a0 += xv.w * p3.x; a1 += xv.w * p3.y;
            }
        }
        const int row = row0 + row_local;
        const float m = mask[row];
        const int k0 = 2 * lane;
        float v0 = (rs * (a0 - mu * sW_sm[k0    ]) + b[k0    ]) * m;
        float v1 = (rs * (a1 - mu * sW_sm[k0 + 1]) + b[k0 + 1]) * m;
        const int s = row >> 9, ip = row & 511;
        if (lane < 16) {
            *(float2*)&g_Lbuf[((size_t)ip * S_DIM + s) * PROJ + k0] = make_float2(v0, v1);
        } else {
            *(float2*)&g_Rbuf[((size_t)s * L_DIM + ip) * PROJ + (k0 - 32)] = make_float2(v0, v1);
        }
    }
}

// ---------------------------------------------------------------------------
// Kernel B (occ 2): per (i, 16-wide j-tile)
//  stage 1: G[j][d][e] = sum_s l[s,i,d]*r[s,j,e]   (r ring-3, 1 sync/chunk)
//  stage 2: out[j,f] = sum_de G * W, W streamed per-d (ring-2, 2 sync/d)
// smem floats:
//   [0,4096)       l_sm            (stage2: W buf 0; epilogue: pbuf lo)
//   [4096,10240)   rc ring-3 x2048 (stage2: W buf 1 in [4096,8192); pbuf hi)
//   [10240,26624)  G [j][d][e]     (pre-stage1: mjs alias)
//   [26624,26640)  normr
//   [26640,26768)  mi
// ---------------------------------------------------------------------------
#define KB_G_OFF   10240
#define KB_NR_OFF  26624
#define KB_MI_OFF  26640
#define KB_SMEM_FLOATS 26768

__global__ void __launch_bounds__(256, 2) Node2Edge_kB(
    const float* __restrict__ Wout, const float* __restrict__ bias,
    const float* __restrict__ mask, float* __restrict__ out)
{
    extern __shared__ float smb[];
    float* l_sm  = smb;
    float* rc    = smb + 4096;
    float* G_sm  = smb + KB_G_OFF;
    float* normr = smb + KB_NR_OFF;
    float* mi    = smb + KB_MI_OFF;
    float* mjs   = G_sm;            // alias before stage 1 writes G

    const int t  = threadIdx.x;
    const int i  = blockIdx.y;
    const int j0 = blockIdx.x * JT;

    // r chunk loader: chunk ch = 4 s rows; rbuf[s][j][e]; ring-3
    auto issue_r = [&](int ch, int buf) {
        unsigned dst0 = (unsigned)__cvta_generic_to_shared(rc + buf * 2048);
        #pragma unroll
        for (int q = 0; q < 2; q++) {
            int v = t + 256 * q;             // 512 float4
            int e4 = v & 7, j = (v >> 3) & 15, s = v >> 7;
            unsigned dst = dst0 + (unsigned)(((s * JT + j) * 32 + e4 * 4) * 4);
            const float* src = g_Rbuf + ((size_t)(ch * 4 + s) * L_DIM + j0 + j) * PROJ + e4 * 4;
            cp16(dst, src);
        }
        cpcommit();
    };
    issue_r(0, 0);
    issue_r(1, 1);

    // l for row i
    {
        const float4* Ls = (const float4*)(g_Lbuf + (size_t)i * S_DIM * PROJ);
        float4* Ld = (float4*)l_sm;
        #pragma unroll
        for (int q = 0; q < 4; q++) Ld[t + 256 * q] = Ls[t + 256 * q];
    }
    // masks
    if (t < 128) mi[t] = mask[t * L_DIM + i];
    #pragma unroll
    for (int q = 0; q < 8; q++) {
        int v = t + 256 * q;                 // 2048 = 128 s x 16 j
        int s = v >> 4, jm = v & 15;
        mjs[v] = mask[s * L_DIM + j0 + jm];
    }
    __syncthreads();
    if (t < JT) {
        float acc = 0.f;
        #pragma unroll 8
        for (int s = 0; s < S_DIM; s++) acc += mi[s] * mjs[s * JT + t];
        normr[t] = 1.0f / (acc + 0.001f);
    }

    // ===== stage 1 ===== (ring-3: one sync per chunk)
    const int e  = t & 31;
    const int jq = t >> 5;                   // warp -> j pair {2jq, 2jq+1}
    ull acc[2][16];
    #pragma unroll
    for (int a = 0; a < 2; a++)
        #pragma unroll
        for (int d2 = 0; d2 < 16; d2++) acc[a][d2] = 0ULL;

    #pragma unroll 1
    for (int ch = 0; ch < 32; ch++) {
        // sync: all warps finished compute(ch-1) -> buf[(ch+2)%3] (== (ch-1)%3) is free;
        // first iter doubles as the mjs/normr barrier.
        __syncthreads();
        if (ch + 2 < 32) { issue_r(ch + 2, (ch + 2) % 3); cpwait2(); }
        else if (ch + 1 < 32) { cpwait1(); }
        else { cpwait0(); }
        const float* rbuf = rc + (ch % 3) * 2048;
        #pragma unroll
        for (int s = 0; s < 4; s++) {
            ull lv[16];
            const ulonglong2* lrow = (const ulonglong2*)(l_sm + (ch * 4 + s) * 32);
            #pragma unroll
            for (int q = 0; q < 8; q++) { ulonglong2 u = lrow[q]; lv[2*q] = u.x; lv[2*q+1] = u.y; }
            #pragma unroll
            for (int jj = 0; jj < 2; jj++) {
                float rv = rbuf[(s * JT + jq * 2 + jj) * 32 + e];
                ull rr = pack2(rv, rv);
                #pragma unroll
                for (int d2 = 0; d2 < 16; d2++) fma2(acc[jj][d2], lv[d2], rr);
            }
        }
    }
    __syncthreads();   // all reads of l_sm / rc done before W streams overwrite

    // W streamer: per d, 4096 floats into [buf*4096, buf*4096+4096)
    auto issue_w = [&](int d, int buf) {
        unsigned dst0 = (unsigned)__cvta_generic_to_shared(smb + buf * 4096);
        const float* src0 = Wout + (size_t)d * 4096;
        #pragma unroll
        for (int q = 0; q < 4; q++) {
            int v = t + 256 * q;             // 1024 float4
            cp16(dst0 + (unsigned)(v * 16), src0 + v * 4);
        }
        cpcommit();
    };
    issue_w(0, 0);

    // write G[j][d][e]
    #pragma unroll
    for (int jj = 0; jj < 2; jj++) {
        const int j = jq * 2 + jj;
        #pragma unroll
        for (int d2 = 0; d2 < 16; d2++) {
            float g0, g1; unpack2(acc[jj][d2], g0, g1);
            G_sm[(j * 32 + 2 * d2    ) * 32 + e] = g0;
            G_sm[(j * 32 + 2 * d2 + 1) * 32 + e] = g1;
        }
    }
    __syncthreads();

    // ===== stage 2 =====
    const int fq = t & 31;                   // f = 4*fq
    const int w  = t >> 5;
    const int eh = w & 3;                    // e block [eh*8, eh*8+8)
    const int jh = w >> 2;                   // j block [jh*8, jh*8+8)
    ull a2[8][2];
    #pragma unroll
    for (int j8 = 0; j8 < 8; j8++) { a2[j8][0] = 0ULL; a2[j8][1] = 0ULL; }

    #pragma unroll 1
    for (int d = 0; d < 32; d++) {
        if (d + 1 < 32) { issue_w(d + 1, (d + 1) & 1); cpwait1(); }
        else            { cpwait0(); }
        __syncthreads();
        const float* wb = smb + (d & 1) * 4096;
        #pragma unroll
        for (int eq = 0; eq < 2; eq++) {
            const int e0 = eh * 8 + eq * 4;
            float4 gv[8];
            #pragma unroll
            for (int j8 = 0; j8 < 8; j8++)
                gv[j8] = *(const float4*)&G_sm[((jh * 8 + j8) * 32 + d) * 32 + e0];
            #pragma unroll
            for (int ee = 0; ee < 4; ee++) {
                float4 wv = *(const float4*)&wb[(e0 + ee) * OUT_F + 4 * fq];
                ull w01 = pack2(wv.x, wv.y);
                ull w23 = pack2(wv.z, wv.w);
                #pragma unroll
                for (int j8 = 0; j8 < 8; j8++) {
                    float g = (ee == 0) ? gv[j8].x : (ee == 1) ? gv[j8].y
                            : (ee == 2) ? gv[j8].z : gv[j8].w;
                    ull gg = pack2(g, g);
                    fma2(a2[j8][0], w01, gg);
                    fma2(a2[j8][1], w23, gg);
                }
            }
        }
        __syncthreads();
    }

    // partials -> smem [0, 8192): pbuf[(eh*16 + j)*128 + 4*fq]
    float* pbuf = smb;
    #pragma unroll
    for (int j8 = 0; j8 < 8; j8++) {
        float v0, v1, v2, v3;
        unpack2(a2[j8][0], v0, v1);
        unpack2(a2[j8][1], v2, v3);
        *(float4*)&pbuf[((eh * JT + jh * 8 + j8) * OUT_F) + 4 * fq] = make_float4(v0, v1, v2, v3);
    }
    __syncthreads();

    // reduce 4 eh groups + epilogue. Tile = 16j x 128f = 512 float4 -> 2/thread.
    #pragma unroll
    for (int q = 0; q < 2; q++) {
        int idx4 = t + 256 * q;
        int j = idx4 >> 5;
        const float4* p = (const float4*)pbuf;
        float4 s0 = p[idx4];
        float4 s1 = p[idx4 + 512];
        float4 s2 = p[idx4 + 1024];
        float4 s3 = p[idx4 + 1536];
        float4 bb = ((const float4*)bias)[idx4 & 31];
        float nr = normr[j];
        float4 o;
        o.x = (s0.x + s1.x + s2.x + s3.x + bb.x) * nr;
        o.y = (s0.y + s1.y + s2.y + s3.y + bb.y) * nr;
        o.z = (s0.z + s1.z + s2.z + s3.z + bb.z) * nr;
        o.w = (s0.w + s1.w + s2.w + s3.w + bb.w) * nr;
        ((float4*)(out + (size_t)i * (L_DIM * OUT_F) + (size_t)j0 * OUT_F))[idx4] = o;
    }
}

// ---------------------------------------------------------------------------
extern "C" void kernel_launch(void* const* d_in, const int* in_sizes, int n_in,
                              void* d_out, int out_size)
{
    const float* node_repr = (const float*)d_in[0];
    const float* mask      = (const float*)d_in[1];
    const float* w_proj    = (const float*)d_in[2];
    const float* b_proj    = (const float*)d_in[3];
    const float* out_w     = (const float*)d_in[4];
    const float* out_bias  = (const float*)d_in[5];
    float* out = (float*)d_out;

    const int smemA = KA_SMEM_FLOATS * 4;
    const int smemB = KB_SMEM_FLOATS * 4;
    cudaFuncSetAttribute(Node2Edge_kA, cudaFuncAttributeMaxDynamicSharedMemorySize, smemA);
    cudaFuncSetAttribute(Node2Edge_kB, cudaFuncAttributeMaxDynamicSharedMemorySize, smemB);

    Node2Edge_kA<<<(S_DIM * L_DIM) / 32, 256, smemA>>>(node_repr, mask, w_proj, b_proj);
    Node2Edge_kB<<<dim3(L_DIM / JT, L_DIM), 256, smemB>>>(out_w, out_bias, mask, out);
}